// round 3
// baseline (speedup 1.0000x reference)
#include <cuda_runtime.h>

#define N_NODES 100000
#define N_EDGES 1600000
#define DIM     128
#define ALPHA   4

// ---------------- scratch (device globals; no allocations allowed) ----------
__device__ float g_hw[(size_t)N_NODES * DIM];   // h @ W.T for current layer
__device__ float g_deg[N_NODES];
__device__ float g_dinv[N_NODES];
__device__ int   g_cnt[N_NODES];
__device__ int   g_off[N_NODES + 1];
__device__ int   g_cursor[N_NODES];
__device__ int   g_srow[N_EDGES];               // source row, sorted by dst col
__device__ float g_snorm[N_EDGES];              // norm coef, sorted by dst col

// ---------------- GEMM: out[n][o] = act(sum_k in[n][k] * W[o][k] + b[o]) ----
#define GEMM_ROWS    64
#define GEMM_THREADS 256
#define WT_LD        132   // padded lead dim for transposed W in smem

__global__ void gemm_kernel(const float* __restrict__ in,
                            const float* __restrict__ W,
                            const float* __restrict__ bias,
                            float* __restrict__ out,
                            int n_rows, int do_relu)
{
    extern __shared__ float smem[];
    float* Wt = smem;                   // [DIM][WT_LD]  (Wt[k][o] = W[o][k])
    float* hs = smem + DIM * WT_LD;     // [GEMM_ROWS][DIM]

    const int tid  = threadIdx.x;
    const int row0 = blockIdx.x * GEMM_ROWS;

    // load W transposed: coalesced global reads
    #pragma unroll
    for (int i = 0; i < (DIM * DIM) / GEMM_THREADS; i++) {
        int idx = tid + i * GEMM_THREADS;
        int k = idx & (DIM - 1);
        int o = idx >> 7;
        Wt[k * WT_LD + o] = W[o * DIM + k];
    }
    // load 64-row h tile as float4 (coalesced)
    const float4* in4 = (const float4*)in;
    #pragma unroll
    for (int i = 0; i < (GEMM_ROWS * (DIM / 4)) / GEMM_THREADS; i++) {
        int idx = tid + i * GEMM_THREADS;
        int r   = idx >> 5;
        int kk  = idx & 31;
        int row = row0 + r;
        float4 v = make_float4(0.f, 0.f, 0.f, 0.f);
        if (row < n_rows) v = in4[(size_t)row * 32 + kk];
        ((float4*)hs)[idx] = v;
    }
    __syncthreads();

    const int c  = tid & 31;   // column group: cols 4c..4c+3
    const int wr = tid >> 5;   // warp row group: rows 8wr..8wr+7

    float acc[8][4];
    #pragma unroll
    for (int j = 0; j < 8; j++) {
        acc[j][0] = acc[j][1] = acc[j][2] = acc[j][3] = 0.f;
    }

    #pragma unroll 4
    for (int k = 0; k < DIM; k++) {
        float4 w = *(const float4*)&Wt[k * WT_LD + 4 * c];  // conflict-free
        #pragma unroll
        for (int j = 0; j < 8; j++) {
            float h = hs[(wr * 8 + j) * DIM + k];           // warp broadcast
            acc[j][0] += h * w.x;
            acc[j][1] += h * w.y;
            acc[j][2] += h * w.z;
            acc[j][3] += h * w.w;
        }
    }

    float4 b = make_float4(0.f, 0.f, 0.f, 0.f);
    if (bias) b = ((const float4*)bias)[c];
    #pragma unroll
    for (int j = 0; j < 8; j++) {
        int row = row0 + wr * 8 + j;
        if (row < n_rows) {
            float4 v;
            v.x = acc[j][0] + b.x;
            v.y = acc[j][1] + b.y;
            v.z = acc[j][2] + b.z;
            v.w = acc[j][3] + b.w;
            if (do_relu) {
                v.x = fmaxf(v.x, 0.f);
                v.y = fmaxf(v.y, 0.f);
                v.z = fmaxf(v.z, 0.f);
                v.w = fmaxf(v.w, 0.f);
            }
            ((float4*)out)[(size_t)row * 32 + c] = v;
        }
    }
}

// ---------------- per-layer graph prep ------------------------------------
__global__ void clear_kernel()
{
    int i = blockIdx.x * blockDim.x + threadIdx.x;
    if (i < N_NODES) {
        g_deg[i] = 0.f;
        g_cnt[i] = 0;
    }
}

__global__ void deg_kernel(const int* __restrict__ col,
                           const float* __restrict__ attr)
{
    int e = blockIdx.x * blockDim.x + threadIdx.x;
    if (e >= N_EDGES) return;
    int c = col[e];
    atomicAdd(&g_deg[c], attr[e]);
    atomicAdd(&g_cnt[c], 1);
}

__global__ void dinv_kernel()
{
    int i = blockIdx.x * blockDim.x + threadIdx.x;
    if (i < N_NODES) {
        float d = g_deg[i];
        g_dinv[i] = (d > 0.f) ? rsqrtf(d) : 0.f;
    }
}

// single-block exclusive scan of g_cnt -> g_off (+ g_cursor copy)
__global__ void scan_kernel()
{
    __shared__ int sh[1024];
    const int tid   = threadIdx.x;
    const int chunk = (N_NODES + 1023) / 1024;
    const int start = tid * chunk;
    const int end   = min(start + chunk, N_NODES);

    int sum = 0;
    for (int i = start; i < end; i++) sum += g_cnt[i];
    sh[tid] = sum;
    __syncthreads();

    // Hillis-Steele inclusive scan
    for (int ofs = 1; ofs < 1024; ofs <<= 1) {
        int v = (tid >= ofs) ? sh[tid - ofs] : 0;
        __syncthreads();
        sh[tid] += v;
        __syncthreads();
    }

    int run = (tid > 0) ? sh[tid - 1] : 0;
    for (int i = start; i < end; i++) {
        g_off[i]    = run;
        g_cursor[i] = run;
        run += g_cnt[i];
    }
    if (tid == 1023) g_off[N_NODES] = sh[1023];
}

// counting-sort edges by destination; materialize (row, norm) in sorted order
__global__ void bin_kernel(const int* __restrict__ row,
                           const int* __restrict__ col,
                           const float* __restrict__ attr)
{
    int e = blockIdx.x * blockDim.x + threadIdx.x;
    if (e >= N_EDGES) return;
    int r = row[e];
    int c = col[e];
    int p = atomicAdd(&g_cursor[c], 1);
    g_srow[p]  = r;
    g_snorm[p] = g_dinv[r] * attr[e] * g_dinv[c];
}

// one warp per destination node: register accumulation, bias+relu fused,
// output written exactly once (no global atomics on the 128-wide rows)
__global__ void gather_kernel(const float* __restrict__ bias,
                              float* __restrict__ out)
{
    const int warp = (blockIdx.x * blockDim.x + threadIdx.x) >> 5;
    const int lane = threadIdx.x & 31;
    if (warp >= N_NODES) return;

    const int s = g_off[warp];
    const int e = g_off[warp + 1];

    float4 acc = make_float4(0.f, 0.f, 0.f, 0.f);
    const float4* hw4 = (const float4*)g_hw;

    for (int p = s; p < e; p++) {
        int   r  = g_srow[p];          // warp-broadcast
        float nm = g_snorm[p];         // warp-broadcast
        float4 v = hw4[(size_t)r * 32 + lane];  // coalesced 512B gather
        acc.x += nm * v.x;
        acc.y += nm * v.y;
        acc.z += nm * v.z;
        acc.w += nm * v.w;
    }

    float4 b = ((const float4*)bias)[lane];
    acc.x = fmaxf(acc.x + b.x, 0.f);
    acc.y = fmaxf(acc.y + b.y, 0.f);
    acc.z = fmaxf(acc.z + b.z, 0.f);
    acc.w = fmaxf(acc.w + b.w, 0.f);
    ((float4*)out)[(size_t)warp * 32 + lane] = acc;
}

// ---------------- launch ----------------------------------------------------
extern "C" void kernel_launch(void* const* d_in, const int* in_sizes, int n_in,
                              void* d_out, int out_size)
{
    const float* x      = (const float*)d_in[0];
    const int*   eidx   = (const int*)d_in[1];     // [ALPHA, 2, E] int32
    const float* eattr  = (const float*)d_in[2];   // [ALPHA, E]
    const float* lin_w  = (const float*)d_in[3];
    const float* lin_b  = (const float*)d_in[4];
    const float* conv_w = (const float*)d_in[5];   // [ALPHA, D, D]
    const float* conv_b = (const float*)d_in[6];   // [ALPHA, D]
    float*       out    = (float*)d_out;           // [ALPHA+1, N, D]

    float* hw_ptr = nullptr;
    cudaGetSymbolAddress((void**)&hw_ptr, g_hw);

    const int smem_bytes = (DIM * WT_LD + GEMM_ROWS * DIM) * (int)sizeof(float);
    cudaFuncSetAttribute(gemm_kernel,
                         cudaFuncAttributeMaxDynamicSharedMemorySize, smem_bytes);

    const int gemm_blocks   = (N_NODES + GEMM_ROWS - 1) / GEMM_ROWS;
    const int node_blocks   = (N_NODES + 255) / 256;
    const int edge_blocks   = (N_EDGES + 255) / 256;
    const int gather_blocks = (N_NODES * 32 + 255) / 256;

    // h0 = relu(x @ lin_w.T + lin_b) -> slice 0
    gemm_kernel<<<gemm_blocks, GEMM_THREADS, smem_bytes>>>(
        x, lin_w, lin_b, out, N_NODES, 1);

    for (int i = 0; i < ALPHA; i++) {
        const int*   row  = eidx + (size_t)i * 2 * N_EDGES;
        const int*   col  = row + N_EDGES;
        const float* attr = eattr + (size_t)i * N_EDGES;
        const float* W    = conv_w + (size_t)i * DIM * DIM;
        const float* b    = conv_b + (size_t)i * DIM;
        const float* hin  = out + (size_t)i * N_NODES * DIM;
        float*       hout = out + (size_t)(i + 1) * N_NODES * DIM;

        clear_kernel<<<node_blocks, 256>>>();
        deg_kernel<<<edge_blocks, 256>>>(col, attr);
        dinv_kernel<<<node_blocks, 256>>>();
        scan_kernel<<<1, 1024>>>();
        bin_kernel<<<edge_blocks, 256>>>(row, col, attr);

        // hw = h @ W.T
        gemm_kernel<<<gemm_blocks, GEMM_THREADS, smem_bytes>>>(
            hin, W, nullptr, hw_ptr, N_NODES, 0);

        // out = relu(scatter_sum(norm * hw[row] -> col) + bias)
        gather_kernel<<<gather_blocks, 256>>>(b, hout);
    }
}

// round 7
// speedup vs baseline: 1.4723x; 1.4723x over previous
#include <cuda_runtime.h>
#include <cstdint>

#define N_NODES 100000
#define N_EDGES 1600000
#define DIM     128
#define ALPHA   4

// ---------------- scratch (device globals; no allocations allowed) ----------
__device__ float g_hw[(size_t)N_NODES * DIM];            // h @ W.T for current layer
__device__ float g_deg[ALPHA * N_NODES];
__device__ float g_dinv[ALPHA * N_NODES];
__device__ int   g_cnt[ALPHA * N_NODES];
__device__ int   g_off[ALPHA * (N_NODES + 1)];
__device__ int   g_cursor[ALPHA * N_NODES];
__device__ int   g_srow[(size_t)ALPHA * N_EDGES];        // src row, sorted by dst
__device__ float g_snorm[(size_t)ALPHA * N_EDGES];       // norm coef, sorted by dst

// ============================================================================
// TF32 3-pass GEMM via mma.sync (valid on plain sm_103 target).
// out[r][n] = act(sum_k in[r][k] * W[n][k] (+ b[n]))
// Block tile: M=128 x N=128(full) x K=128. 8 warps (4 M-groups x 2 N-groups).
// Warp tile: 32x64 = 2(m16) x 8(n8) mma tiles, fp32 accum in registers.
// ============================================================================
#define TILE_M   128
#define GT       256
#define LDA      132          // padded smem lead dim (floats)

__device__ __forceinline__ uint32_t f2tf32(float x) {
    uint32_t r;
    asm("cvt.rna.tf32.f32 %0, %1;" : "=r"(r) : "f"(x));
    return r;
}

__device__ __forceinline__ void mma_tf32(float c[4],
                                         uint32_t a0, uint32_t a1, uint32_t a2, uint32_t a3,
                                         uint32_t b0, uint32_t b1) {
    asm volatile(
        "mma.sync.aligned.m16n8k8.row.col.f32.tf32.tf32.f32 "
        "{%0,%1,%2,%3}, {%4,%5,%6,%7}, {%8,%9}, {%0,%1,%2,%3};"
        : "+f"(c[0]), "+f"(c[1]), "+f"(c[2]), "+f"(c[3])
        : "r"(a0), "r"(a1), "r"(a2), "r"(a3), "r"(b0), "r"(b1));
}

__global__ void __launch_bounds__(GT, 1)
gemm_mma(const float* __restrict__ in, const float* __restrict__ W,
         const float* __restrict__ bias, float* __restrict__ out,
         int n_rows, int do_relu)
{
    extern __shared__ float smem[];
    float* As = smem;                  // [128][LDA] fp32 input tile
    float* Ws = smem + TILE_M * LDA;   // [128][LDA] fp32 weight tile

    const int tid  = threadIdx.x;
    const int wid  = tid >> 5;
    const int lane = tid & 31;
    const int gid  = lane >> 2;        // group id 0..7
    const int tig  = lane & 3;         // thread-in-group 0..3
    const int wm   = wid & 3;          // warp M group (32 rows)
    const int wn   = wid >> 2;         // warp N group (64 cols)
    const int row0 = blockIdx.x * TILE_M;

    // ---- load A tile (128 x 128 f32, zero-padded rows) ----
    const float4* in4 = (const float4*)in;
    #pragma unroll
    for (int i = 0; i < (TILE_M * 32) / GT; i++) {
        int idx = tid + i * GT;
        int r   = idx >> 5;
        int c4  = idx & 31;
        int row = row0 + r;
        float4 v = make_float4(0.f, 0.f, 0.f, 0.f);
        if (row < n_rows) v = in4[(size_t)row * 32 + c4];
        *(float4*)&As[r * LDA + c4 * 4] = v;
    }
    // ---- load W tile (128 x 128 f32) ----
    const float4* W4 = (const float4*)W;
    #pragma unroll
    for (int i = 0; i < (DIM * 32) / GT; i++) {
        int idx = tid + i * GT;
        int r   = idx >> 5;
        int c4  = idx & 31;
        *(float4*)&Ws[r * LDA + c4 * 4] = W4[(size_t)r * 32 + c4];
    }
    __syncthreads();

    float c[2][8][4];
    #pragma unroll
    for (int mi = 0; mi < 2; mi++)
        #pragma unroll
        for (int ni = 0; ni < 8; ni++)
            #pragma unroll
            for (int j = 0; j < 4; j++)
                c[mi][ni][j] = 0.f;

    #pragma unroll
    for (int ks = 0; ks < DIM / 8; ks++) {
        const int k0 = ks * 8;

        // A fragments (2 m16 tiles), split hi/lo in registers
        uint32_t ah[2][4], al[2][4];
        #pragma unroll
        for (int mi = 0; mi < 2; mi++) {
            const int rb = wm * 32 + mi * 16;
            float v0 = As[(rb + gid)     * LDA + k0 + tig];
            float v1 = As[(rb + gid + 8) * LDA + k0 + tig];
            float v2 = As[(rb + gid)     * LDA + k0 + tig + 4];
            float v3 = As[(rb + gid + 8) * LDA + k0 + tig + 4];
            ah[mi][0] = f2tf32(v0); al[mi][0] = f2tf32(v0 - __uint_as_float(ah[mi][0]));
            ah[mi][1] = f2tf32(v1); al[mi][1] = f2tf32(v1 - __uint_as_float(ah[mi][1]));
            ah[mi][2] = f2tf32(v2); al[mi][2] = f2tf32(v2 - __uint_as_float(ah[mi][2]));
            ah[mi][3] = f2tf32(v3); al[mi][3] = f2tf32(v3 - __uint_as_float(ah[mi][3]));
        }
        // B fragments (8 n8 tiles): B[k][n] = W[n][k]
        uint32_t bh[8][2], bl[8][2];
        #pragma unroll
        for (int ni = 0; ni < 8; ni++) {
            const int col = wn * 64 + ni * 8 + gid;
            float v0 = Ws[col * LDA + k0 + tig];
            float v1 = Ws[col * LDA + k0 + tig + 4];
            bh[ni][0] = f2tf32(v0); bl[ni][0] = f2tf32(v0 - __uint_as_float(bh[ni][0]));
            bh[ni][1] = f2tf32(v1); bl[ni][1] = f2tf32(v1 - __uint_as_float(bh[ni][1]));
        }

        #pragma unroll
        for (int mi = 0; mi < 2; mi++)
            #pragma unroll
            for (int ni = 0; ni < 8; ni++) {
                mma_tf32(c[mi][ni], ah[mi][0], ah[mi][1], ah[mi][2], ah[mi][3],
                         bh[ni][0], bh[ni][1]);
                mma_tf32(c[mi][ni], al[mi][0], al[mi][1], al[mi][2], al[mi][3],
                         bh[ni][0], bh[ni][1]);
                mma_tf32(c[mi][ni], ah[mi][0], ah[mi][1], ah[mi][2], ah[mi][3],
                         bl[ni][0], bl[ni][1]);
            }
    }
    __syncthreads();

    // ---- epilogue: frags -> smem stage (reuse As) -> coalesced float4 out ----
    float* stage = As;   // [128][LDA]
    #pragma unroll
    for (int mi = 0; mi < 2; mi++) {
        const int rb = wm * 32 + mi * 16;
        #pragma unroll
        for (int ni = 0; ni < 8; ni++) {
            const int cb = wn * 64 + ni * 8 + tig * 2;
            *(float2*)&stage[(rb + gid)     * LDA + cb] = make_float2(c[mi][ni][0], c[mi][ni][1]);
            *(float2*)&stage[(rb + gid + 8) * LDA + cb] = make_float2(c[mi][ni][2], c[mi][ni][3]);
        }
    }
    __syncthreads();

    #pragma unroll
    for (int i = 0; i < (TILE_M * 32) / GT; i++) {
        int idx = tid + i * GT;
        int r   = idx >> 5;
        int c4  = idx & 31;
        int row = row0 + r;
        if (row < n_rows) {
            float4 v = *(float4*)&stage[r * LDA + c4 * 4];
            if (bias) {
                const float4 b = *(const float4*)&bias[c4 * 4];
                v.x += b.x; v.y += b.y; v.z += b.z; v.w += b.w;
            }
            if (do_relu) {
                v.x = fmaxf(v.x, 0.f); v.y = fmaxf(v.y, 0.f);
                v.z = fmaxf(v.z, 0.f); v.w = fmaxf(v.w, 0.f);
            }
            *(float4*)&out[(size_t)row * DIM + c4 * 4] = v;
        }
    }
}

// ============================================================================
// batched per-layer graph prep (all ALPHA layers at once)
// ============================================================================
__global__ void clear_kernel()
{
    int i = blockIdx.x * blockDim.x + threadIdx.x;
    if (i < ALPHA * N_NODES) {
        g_deg[i] = 0.f;
        g_cnt[i] = 0;
    }
}

__global__ void deg_kernel(const int* __restrict__ eidx, const float* __restrict__ eattr)
{
    int e = blockIdx.x * blockDim.x + threadIdx.x;
    int l = blockIdx.y;
    if (e >= N_EDGES) return;
    int c = eidx[(size_t)l * 2 * N_EDGES + N_EDGES + e];
    atomicAdd(&g_deg[l * N_NODES + c], eattr[(size_t)l * N_EDGES + e]);
    atomicAdd(&g_cnt[l * N_NODES + c], 1);
}

__global__ void dinv_kernel()
{
    int i = blockIdx.x * blockDim.x + threadIdx.x;
    if (i < ALPHA * N_NODES) {
        float d = g_deg[i];
        g_dinv[i] = (d > 0.f) ? rsqrtf(d) : 0.f;
    }
}

// one block per layer: exclusive scan of g_cnt -> g_off (+ cursor copy)
__global__ void scan_kernel()
{
    __shared__ int sh[1024];
    const int l     = blockIdx.x;
    const int tid   = threadIdx.x;
    const int* cnt  = g_cnt + l * N_NODES;
    int* off        = g_off + l * (N_NODES + 1);
    int* cur        = g_cursor + l * N_NODES;
    const int chunk = (N_NODES + 1023) / 1024;
    const int start = tid * chunk;
    const int end   = min(start + chunk, N_NODES);

    int sum = 0;
    for (int i = start; i < end; i++) sum += cnt[i];
    sh[tid] = sum;
    __syncthreads();
    for (int ofs = 1; ofs < 1024; ofs <<= 1) {
        int v = (tid >= ofs) ? sh[tid - ofs] : 0;
        __syncthreads();
        sh[tid] += v;
        __syncthreads();
    }
    int run = (tid > 0) ? sh[tid - 1] : 0;
    for (int i = start; i < end; i++) {
        off[i] = run;
        cur[i] = run;
        run += cnt[i];
    }
    if (tid == 1023) off[N_NODES] = sh[1023];
}

__global__ void bin_kernel(const int* __restrict__ eidx, const float* __restrict__ eattr)
{
    int e = blockIdx.x * blockDim.x + threadIdx.x;
    int l = blockIdx.y;
    if (e >= N_EDGES) return;
    int r = eidx[(size_t)l * 2 * N_EDGES + e];
    int c = eidx[(size_t)l * 2 * N_EDGES + N_EDGES + e];
    int p = atomicAdd(&g_cursor[l * N_NODES + c], 1);
    g_srow[(size_t)l * N_EDGES + p]  = r;
    g_snorm[(size_t)l * N_EDGES + p] =
        g_dinv[l * N_NODES + r] * eattr[(size_t)l * N_EDGES + e] * g_dinv[l * N_NODES + c];
}

// one warp per destination node: register accumulation, bias+relu fused
__global__ void gather_kernel(int l, const float* __restrict__ bias, float* __restrict__ out)
{
    const int warp = (blockIdx.x * blockDim.x + threadIdx.x) >> 5;
    const int lane = threadIdx.x & 31;
    if (warp >= N_NODES) return;

    const int s = g_off[l * (N_NODES + 1) + warp];
    const int e = g_off[l * (N_NODES + 1) + warp + 1];
    const int*   srow  = g_srow  + (size_t)l * N_EDGES;
    const float* snorm = g_snorm + (size_t)l * N_EDGES;

    float4 acc = make_float4(0.f, 0.f, 0.f, 0.f);
    const float4* hw4 = (const float4*)g_hw;

    for (int p = s; p < e; p++) {
        int   r  = srow[p];
        float nm = snorm[p];
        float4 v = hw4[(size_t)r * 32 + lane];
        acc.x += nm * v.x;
        acc.y += nm * v.y;
        acc.z += nm * v.z;
        acc.w += nm * v.w;
    }

    float4 b = ((const float4*)bias)[lane];
    acc.x = fmaxf(acc.x + b.x, 0.f);
    acc.y = fmaxf(acc.y + b.y, 0.f);
    acc.z = fmaxf(acc.z + b.z, 0.f);
    acc.w = fmaxf(acc.w + b.w, 0.f);
    ((float4*)out)[(size_t)warp * 32 + lane] = acc;
}

// ---------------- launch ----------------------------------------------------
extern "C" void kernel_launch(void* const* d_in, const int* in_sizes, int n_in,
                              void* d_out, int out_size)
{
    const float* x      = (const float*)d_in[0];
    const int*   eidx   = (const int*)d_in[1];     // [ALPHA, 2, E] (int32 payload)
    const float* eattr  = (const float*)d_in[2];   // [ALPHA, E]
    const float* lin_w  = (const float*)d_in[3];
    const float* lin_b  = (const float*)d_in[4];
    const float* conv_w = (const float*)d_in[5];   // [ALPHA, D, D]
    const float* conv_b = (const float*)d_in[6];   // [ALPHA, D]
    float*       out    = (float*)d_out;           // [ALPHA+1, N, D]

    float* hw_ptr = nullptr;
    cudaGetSymbolAddress((void**)&hw_ptr, g_hw);

    const int smem_bytes = 2 * TILE_M * LDA * (int)sizeof(float);   // 135168
    cudaFuncSetAttribute(gemm_mma, cudaFuncAttributeMaxDynamicSharedMemorySize, smem_bytes);

    const int gemm_blocks      = (N_NODES + TILE_M - 1) / TILE_M;
    const int all_node_blocks  = (ALPHA * N_NODES + 255) / 256;
    const int edge_blocks      = (N_EDGES + 255) / 256;
    const int gather_blocks    = (N_NODES * 32 + 255) / 256;

    // --- batched prep for all layers (independent of h) ---
    clear_kernel<<<all_node_blocks, 256>>>();
    deg_kernel<<<dim3(edge_blocks, ALPHA), 256>>>(eidx, eattr);
    dinv_kernel<<<all_node_blocks, 256>>>();
    scan_kernel<<<ALPHA, 1024>>>();
    bin_kernel<<<dim3(edge_blocks, ALPHA), 256>>>(eidx, eattr);

    // h0 = relu(x @ lin_w.T + lin_b) -> slice 0       (launch #5: profiled)
    gemm_mma<<<gemm_blocks, GT, smem_bytes>>>(x, lin_w, lin_b, out, N_NODES, 1);

    for (int i = 0; i < ALPHA; i++) {
        const float* W    = conv_w + (size_t)i * DIM * DIM;
        const float* b    = conv_b + (size_t)i * DIM;
        const float* hin  = out + (size_t)i * N_NODES * DIM;
        float*       hout = out + (size_t)(i + 1) * N_NODES * DIM;

        gemm_mma<<<gemm_blocks, GT, smem_bytes>>>(hin, W, nullptr, hw_ptr, N_NODES, 0);
        gather_kernel<<<gather_blocks, 256>>>(i, b, hout);
    }
}

// round 8
// speedup vs baseline: 1.7253x; 1.1718x over previous
#include <cuda_runtime.h>
#include <cstdint>

#define N_NODES 100000
#define N_EDGES 1600000
#define DIM     128
#define ALPHA   4

#define SCAN_BLK   1024
#define SCAN_ELEMS 2048
#define NB ((N_NODES + SCAN_ELEMS - 1) / SCAN_ELEMS)   // 49

// ---------------- scratch (device globals; no allocations allowed) ----------
__device__ float g_hw[(size_t)N_NODES * DIM];            // h @ W.T for current layer
__device__ float g_deg[ALPHA * N_NODES];
__device__ float g_dinv[ALPHA * N_NODES];
__device__ int   g_cnt[ALPHA * N_NODES];
__device__ int   g_off[ALPHA * (N_NODES + 1)];
__device__ int   g_cursor[ALPHA * N_NODES];
__device__ int   g_bsum[ALPHA * NB];
__device__ int   g_srow[(size_t)ALPHA * N_EDGES];        // src row, sorted by dst
__device__ float g_snorm[(size_t)ALPHA * N_EDGES];       // norm coef, sorted by dst

// ============================================================================
// TF32 3-pass GEMM via mma.sync (valid on plain sm_103 target).
// out[r][n] = act(sum_k in[r][k] * W[n][k] (+ b[n]))
// ============================================================================
#define TILE_M   128
#define GT       256
#define LDA      132          // padded smem lead dim (floats)

__device__ __forceinline__ uint32_t f2tf32(float x) {
    uint32_t r;
    asm("cvt.rna.tf32.f32 %0, %1;" : "=r"(r) : "f"(x));
    return r;
}

__device__ __forceinline__ void mma_tf32(float c[4],
                                         uint32_t a0, uint32_t a1, uint32_t a2, uint32_t a3,
                                         uint32_t b0, uint32_t b1) {
    asm volatile(
        "mma.sync.aligned.m16n8k8.row.col.f32.tf32.tf32.f32 "
        "{%0,%1,%2,%3}, {%4,%5,%6,%7}, {%8,%9}, {%0,%1,%2,%3};"
        : "+f"(c[0]), "+f"(c[1]), "+f"(c[2]), "+f"(c[3])
        : "r"(a0), "r"(a1), "r"(a2), "r"(a3), "r"(b0), "r"(b1));
}

__global__ void __launch_bounds__(GT, 1)
gemm_mma(const float* __restrict__ in, const float* __restrict__ W,
         const float* __restrict__ bias, float* __restrict__ out,
         int n_rows, int do_relu)
{
    extern __shared__ float smem[];
    float* As = smem;                  // [128][LDA] fp32 input tile
    float* Ws = smem + TILE_M * LDA;   // [128][LDA] fp32 weight tile

    const int tid  = threadIdx.x;
    const int wid  = tid >> 5;
    const int lane = tid & 31;
    const int gid  = lane >> 2;
    const int tig  = lane & 3;
    const int wm   = wid & 3;
    const int wn   = wid >> 2;
    const int row0 = blockIdx.x * TILE_M;

    const float4* in4 = (const float4*)in;
    #pragma unroll
    for (int i = 0; i < (TILE_M * 32) / GT; i++) {
        int idx = tid + i * GT;
        int r   = idx >> 5;
        int c4  = idx & 31;
        int row = row0 + r;
        float4 v = make_float4(0.f, 0.f, 0.f, 0.f);
        if (row < n_rows) v = in4[(size_t)row * 32 + c4];
        *(float4*)&As[r * LDA + c4 * 4] = v;
    }
    const float4* W4 = (const float4*)W;
    #pragma unroll
    for (int i = 0; i < (DIM * 32) / GT; i++) {
        int idx = tid + i * GT;
        int r   = idx >> 5;
        int c4  = idx & 31;
        *(float4*)&Ws[r * LDA + c4 * 4] = W4[(size_t)r * 32 + c4];
    }
    __syncthreads();

    float c[2][8][4];
    #pragma unroll
    for (int mi = 0; mi < 2; mi++)
        #pragma unroll
        for (int ni = 0; ni < 8; ni++)
            #pragma unroll
            for (int j = 0; j < 4; j++)
                c[mi][ni][j] = 0.f;

    #pragma unroll
    for (int ks = 0; ks < DIM / 8; ks++) {
        const int k0 = ks * 8;

        uint32_t ah[2][4], al[2][4];
        #pragma unroll
        for (int mi = 0; mi < 2; mi++) {
            const int rb = wm * 32 + mi * 16;
            float v0 = As[(rb + gid)     * LDA + k0 + tig];
            float v1 = As[(rb + gid + 8) * LDA + k0 + tig];
            float v2 = As[(rb + gid)     * LDA + k0 + tig + 4];
            float v3 = As[(rb + gid + 8) * LDA + k0 + tig + 4];
            ah[mi][0] = f2tf32(v0); al[mi][0] = f2tf32(v0 - __uint_as_float(ah[mi][0]));
            ah[mi][1] = f2tf32(v1); al[mi][1] = f2tf32(v1 - __uint_as_float(ah[mi][1]));
            ah[mi][2] = f2tf32(v2); al[mi][2] = f2tf32(v2 - __uint_as_float(ah[mi][2]));
            ah[mi][3] = f2tf32(v3); al[mi][3] = f2tf32(v3 - __uint_as_float(ah[mi][3]));
        }
        uint32_t bh[8][2], bl[8][2];
        #pragma unroll
        for (int ni = 0; ni < 8; ni++) {
            const int col = wn * 64 + ni * 8 + gid;
            float v0 = Ws[col * LDA + k0 + tig];
            float v1 = Ws[col * LDA + k0 + tig + 4];
            bh[ni][0] = f2tf32(v0); bl[ni][0] = f2tf32(v0 - __uint_as_float(bh[ni][0]));
            bh[ni][1] = f2tf32(v1); bl[ni][1] = f2tf32(v1 - __uint_as_float(bh[ni][1]));
        }

        #pragma unroll
        for (int mi = 0; mi < 2; mi++)
            #pragma unroll
            for (int ni = 0; ni < 8; ni++) {
                mma_tf32(c[mi][ni], ah[mi][0], ah[mi][1], ah[mi][2], ah[mi][3],
                         bh[ni][0], bh[ni][1]);
                mma_tf32(c[mi][ni], al[mi][0], al[mi][1], al[mi][2], al[mi][3],
                         bh[ni][0], bh[ni][1]);
                mma_tf32(c[mi][ni], ah[mi][0], ah[mi][1], ah[mi][2], ah[mi][3],
                         bl[ni][0], bl[ni][1]);
            }
    }
    __syncthreads();

    float* stage = As;
    #pragma unroll
    for (int mi = 0; mi < 2; mi++) {
        const int rb = wm * 32 + mi * 16;
        #pragma unroll
        for (int ni = 0; ni < 8; ni++) {
            const int cb = wn * 64 + ni * 8 + tig * 2;
            *(float2*)&stage[(rb + gid)     * LDA + cb] = make_float2(c[mi][ni][0], c[mi][ni][1]);
            *(float2*)&stage[(rb + gid + 8) * LDA + cb] = make_float2(c[mi][ni][2], c[mi][ni][3]);
        }
    }
    __syncthreads();

    #pragma unroll
    for (int i = 0; i < (TILE_M * 32) / GT; i++) {
        int idx = tid + i * GT;
        int r   = idx >> 5;
        int c4  = idx & 31;
        int row = row0 + r;
        if (row < n_rows) {
            float4 v = *(float4*)&stage[r * LDA + c4 * 4];
            if (bias) {
                const float4 b = *(const float4*)&bias[c4 * 4];
                v.x += b.x; v.y += b.y; v.z += b.z; v.w += b.w;
            }
            if (do_relu) {
                v.x = fmaxf(v.x, 0.f); v.y = fmaxf(v.y, 0.f);
                v.z = fmaxf(v.z, 0.f); v.w = fmaxf(v.w, 0.f);
            }
            *(float4*)&out[(size_t)row * DIM + c4 * 4] = v;
        }
    }
}

// ============================================================================
// batched per-layer graph prep (all ALPHA layers at once)
// ============================================================================
__global__ void clear_kernel()
{
    int i = blockIdx.x * blockDim.x + threadIdx.x;
    if (i < ALPHA * N_NODES) {
        g_deg[i] = 0.f;
        g_cnt[i] = 0;
    }
}

__global__ void deg_kernel(const int* __restrict__ eidx, const float* __restrict__ eattr)
{
    int e = blockIdx.x * blockDim.x + threadIdx.x;
    int l = blockIdx.y;
    if (e >= N_EDGES) return;
    int c = eidx[(size_t)l * 2 * N_EDGES + N_EDGES + e];
    atomicAdd(&g_deg[l * N_NODES + c], eattr[(size_t)l * N_EDGES + e]);
    atomicAdd(&g_cnt[l * N_NODES + c], 1);
}

__global__ void dinv_kernel()
{
    int i = blockIdx.x * blockDim.x + threadIdx.x;
    if (i < ALPHA * N_NODES) {
        float d = g_deg[i];
        g_dinv[i] = (d > 0.f) ? rsqrtf(d) : 0.f;
    }
}

// ---- 3-phase multi-block exclusive scan of g_cnt -> g_off / g_cursor ------
__global__ void scan_p1()   // grid (NB, ALPHA), block SCAN_BLK
{
    const int l = blockIdx.y, b = blockIdx.x, tid = threadIdx.x;
    const int i0 = b * SCAN_ELEMS + tid * 2;
    int s = 0;
    if (i0     < N_NODES) s += g_cnt[l * N_NODES + i0];
    if (i0 + 1 < N_NODES) s += g_cnt[l * N_NODES + i0 + 1];

    __shared__ int sh[SCAN_BLK];
    sh[tid] = s;
    __syncthreads();
    #pragma unroll
    for (int ofs = SCAN_BLK / 2; ofs > 0; ofs >>= 1) {
        if (tid < ofs) sh[tid] += sh[tid + ofs];
        __syncthreads();
    }
    if (tid == 0) g_bsum[l * NB + b] = sh[0];
}

__global__ void scan_p2()   // 1 block, tiny
{
    int l = threadIdx.x;
    if (l < ALPHA) {
        int run = 0;
        for (int b = 0; b < NB; b++) {
            int v = g_bsum[l * NB + b];
            g_bsum[l * NB + b] = run;
            run += v;
        }
    }
}

__global__ void scan_p3()   // grid (NB, ALPHA), block SCAN_BLK
{
    const int l = blockIdx.y, b = blockIdx.x, tid = threadIdx.x;
    const int i0 = b * SCAN_ELEMS + tid * 2;
    int v0 = 0, v1 = 0;
    if (i0     < N_NODES) v0 = g_cnt[l * N_NODES + i0];
    if (i0 + 1 < N_NODES) v1 = g_cnt[l * N_NODES + i0 + 1];
    const int tsum = v0 + v1;

    __shared__ int sh[SCAN_BLK];
    sh[tid] = tsum;
    __syncthreads();
    #pragma unroll
    for (int ofs = 1; ofs < SCAN_BLK; ofs <<= 1) {
        int x = (tid >= ofs) ? sh[tid - ofs] : 0;
        __syncthreads();
        sh[tid] += x;
        __syncthreads();
    }
    const int texcl = sh[tid] - tsum + g_bsum[l * NB + b];
    if (i0 < N_NODES) {
        g_off[l * (N_NODES + 1) + i0] = texcl;
        g_cursor[l * N_NODES + i0]    = texcl;
    }
    if (i0 + 1 < N_NODES) {
        g_off[l * (N_NODES + 1) + i0 + 1] = texcl + v0;
        g_cursor[l * N_NODES + i0 + 1]    = texcl + v0;
    }
    if (b == NB - 1 && tid == SCAN_BLK - 1)
        g_off[l * (N_NODES + 1) + N_NODES] = texcl + tsum;
}

__global__ void bin_kernel(const int* __restrict__ eidx, const float* __restrict__ eattr)
{
    int e = blockIdx.x * blockDim.x + threadIdx.x;
    int l = blockIdx.y;
    if (e >= N_EDGES) return;
    int r = eidx[(size_t)l * 2 * N_EDGES + e];
    int c = eidx[(size_t)l * 2 * N_EDGES + N_EDGES + e];
    int p = atomicAdd(&g_cursor[l * N_NODES + c], 1);
    g_srow[(size_t)l * N_EDGES + p]  = r;
    g_snorm[(size_t)l * N_EDGES + p] =
        g_dinv[l * N_NODES + r] * eattr[(size_t)l * N_EDGES + e] * g_dinv[l * N_NODES + c];
}

// one warp per destination node; x2 unrolled with dual accumulators for MLP
__global__ void gather_kernel(int l, const float* __restrict__ bias, float* __restrict__ out)
{
    const int warp = (blockIdx.x * blockDim.x + threadIdx.x) >> 5;
    const int lane = threadIdx.x & 31;
    if (warp >= N_NODES) return;

    const int s = g_off[l * (N_NODES + 1) + warp];
    const int e = g_off[l * (N_NODES + 1) + warp + 1];
    const int*   srow  = g_srow  + (size_t)l * N_EDGES;
    const float* snorm = g_snorm + (size_t)l * N_EDGES;
    const float4* hw4  = (const float4*)g_hw;

    float4 acc0 = make_float4(0.f, 0.f, 0.f, 0.f);
    float4 acc1 = make_float4(0.f, 0.f, 0.f, 0.f);

    int p = s;
    for (; p + 2 <= e; p += 2) {
        int   r0 = srow[p],     r1 = srow[p + 1];
        float n0 = snorm[p],    n1 = snorm[p + 1];
        float4 v0 = hw4[(size_t)r0 * 32 + lane];
        float4 v1 = hw4[(size_t)r1 * 32 + lane];
        acc0.x += n0 * v0.x; acc0.y += n0 * v0.y; acc0.z += n0 * v0.z; acc0.w += n0 * v0.w;
        acc1.x += n1 * v1.x; acc1.y += n1 * v1.y; acc1.z += n1 * v1.z; acc1.w += n1 * v1.w;
    }
    if (p < e) {
        int   r0 = srow[p];
        float n0 = snorm[p];
        float4 v0 = hw4[(size_t)r0 * 32 + lane];
        acc0.x += n0 * v0.x; acc0.y += n0 * v0.y; acc0.z += n0 * v0.z; acc0.w += n0 * v0.w;
    }

    float4 b = ((const float4*)bias)[lane];
    acc0.x = fmaxf(acc0.x + acc1.x + b.x, 0.f);
    acc0.y = fmaxf(acc0.y + acc1.y + b.y, 0.f);
    acc0.z = fmaxf(acc0.z + acc1.z + b.z, 0.f);
    acc0.w = fmaxf(acc0.w + acc1.w + b.w, 0.f);
    ((float4*)out)[(size_t)warp * 32 + lane] = acc0;
}

// ---------------- launch ----------------------------------------------------
extern "C" void kernel_launch(void* const* d_in, const int* in_sizes, int n_in,
                              void* d_out, int out_size)
{
    const float* x      = (const float*)d_in[0];
    const int*   eidx   = (const int*)d_in[1];     // [ALPHA, 2, E] (int32 payload)
    const float* eattr  = (const float*)d_in[2];   // [ALPHA, E]
    const float* lin_w  = (const float*)d_in[3];
    const float* lin_b  = (const float*)d_in[4];
    const float* conv_w = (const float*)d_in[5];   // [ALPHA, D, D]
    const float* conv_b = (const float*)d_in[6];   // [ALPHA, D]
    float*       out    = (float*)d_out;           // [ALPHA+1, N, D]

    float* hw_ptr = nullptr;
    cudaGetSymbolAddress((void**)&hw_ptr, g_hw);

    const int smem_bytes = 2 * TILE_M * LDA * (int)sizeof(float);   // 135168
    cudaFuncSetAttribute(gemm_mma, cudaFuncAttributeMaxDynamicSharedMemorySize, smem_bytes);

    const int gemm_blocks      = (N_NODES + TILE_M - 1) / TILE_M;
    const int all_node_blocks  = (ALPHA * N_NODES + 255) / 256;
    const int edge_blocks      = (N_EDGES + 255) / 256;
    const int gather_blocks    = (N_NODES * 32 + 255) / 256;

    // --- batched prep for all layers (independent of h) ---
    clear_kernel<<<all_node_blocks, 256>>>();
    deg_kernel<<<dim3(edge_blocks, ALPHA), 256>>>(eidx, eattr);
    dinv_kernel<<<all_node_blocks, 256>>>();
    scan_p1<<<dim3(NB, ALPHA), SCAN_BLK>>>();
    scan_p2<<<1, 128>>>();
    scan_p3<<<dim3(NB, ALPHA), SCAN_BLK>>>();
    bin_kernel<<<dim3(edge_blocks, ALPHA), 256>>>(eidx, eattr);

    // h0 = relu(x @ lin_w.T + lin_b) -> slice 0
    gemm_mma<<<gemm_blocks, GT, smem_bytes>>>(x, lin_w, lin_b, out, N_NODES, 1);

    for (int i = 0; i < ALPHA; i++) {
        const float* W    = conv_w + (size_t)i * DIM * DIM;
        const float* b    = conv_b + (size_t)i * DIM;
        const float* hin  = out + (size_t)i * N_NODES * DIM;
        float*       hout = out + (size_t)(i + 1) * N_NODES * DIM;

        gemm_mma<<<gemm_blocks, GT, smem_bytes>>>(hin, W, nullptr, hw_ptr, N_NODES, 0);
        gather_kernel<<<gather_blocks, 256>>>(i, b, hout);
    }
}